// round 12
// baseline (speedup 1.0000x reference)
#include <cuda_runtime.h>
#include <cuda_bf16.h>
#include <cstdint>

// GAT: B=4, N=4096, C=64
// out = elu( softmax_j( mask(adj>0.5, lrelu(s1+s2)) ) @ h )
// R11: software-pipelined merge — MMA(t) interleaved with phaseB(t+1) at
//      kk-chunk granularity. 3-stage B cp.async, 2-stage W, 1 sync/tile.

#define GB 4
#define GN 4096
#define GC 64
#define TI 64
#define TJ 64
#define NTILES (GN / TJ)
#define ALPHA 0.2f
#define THRESH 0.5f

#define BSTG_SZ 16384     // BH 8KB + BL 8KB
#define WSTG_SZ 16384     // WH 8KB + WL 8KB
#define B_HI    0
#define B_LO    8192
#define W_HI    0
#define W_LO    8192
#define W_BASE  (3 * BSTG_SZ)
#define DSMEM_BYTES (3 * BSTG_SZ + 2 * WSTG_SZ + 1024)

__device__ float g_s1[GB * GN];
__device__ float g_s2[GB * GN];
__device__ __nv_bfloat16 g_hh[GB * GN * GC];
__device__ __nv_bfloat16 g_hl[GB * GN * GC];

// ---------------------------------------------------------------- helpers
static __device__ __forceinline__ uint32_t smem_u32(const void* p) {
    uint32_t a;
    asm("{ .reg .u64 t; cvta.to.shared.u64 t, %1; cvt.u32.u64 %0, t; }"
        : "=r"(a) : "l"(p));
    return a;
}
static __device__ __forceinline__ float fast_ex2(float x) {
    float r; asm("ex2.approx.f32 %0, %1;" : "=f"(r) : "f"(x)); return r;
}
// packs {lo -> low16, hi -> high16}
static __device__ __forceinline__ uint32_t cvt_bf16x2(float lo, float hi) {
    uint32_t r;
    asm("cvt.rn.bf16x2.f32 %0, %1, %2;" : "=r"(r) : "f"(hi), "f"(lo));
    return r;
}
static __device__ __forceinline__ uint32_t sw128(uint32_t b) {
    return b ^ ((b >> 3) & 0x70);
}
#define CP16(dst, src) \
    asm volatile("cp.async.cg.shared.global [%0], [%1], 16;" \
                 :: "r"(dst), "l"(src) : "memory")
#define CP_COMMIT() asm volatile("cp.async.commit_group;" ::: "memory")
#define CP_WAIT1()  asm volatile("cp.async.wait_group 1;" ::: "memory")

static __device__ __forceinline__ void ldmx4(uint32_t* r, uint32_t addr) {
    asm volatile("ldmatrix.sync.aligned.m8n8.x4.shared.b16 {%0,%1,%2,%3}, [%4];"
        : "=r"(r[0]), "=r"(r[1]), "=r"(r[2]), "=r"(r[3]) : "r"(addr));
}
static __device__ __forceinline__ void ldmx4t(uint32_t* r, uint32_t addr) {
    asm volatile("ldmatrix.sync.aligned.m8n8.x4.trans.shared.b16 {%0,%1,%2,%3}, [%4];"
        : "=r"(r[0]), "=r"(r[1]), "=r"(r[2]), "=r"(r[3]) : "r"(addr));
}
static __device__ __forceinline__ void mma_bf16(float* d, const uint32_t* a,
                                                uint32_t b0, uint32_t b1) {
    asm volatile(
        "mma.sync.aligned.m16n8k16.row.col.f32.bf16.bf16.f32 "
        "{%0,%1,%2,%3}, {%4,%5,%6,%7}, {%8,%9}, {%0,%1,%2,%3};"
        : "+f"(d[0]), "+f"(d[1]), "+f"(d[2]), "+f"(d[3])
        : "r"(a[0]), "r"(a[1]), "r"(a[2]), "r"(a[3]), "r"(b0), "r"(b1));
}

// ---------------------------------------------------------------- kernel 1
__global__ void gat_scores_kernel(const float* __restrict__ h,
                                  const float* __restrict__ a) {
    int warp = (blockIdx.x * blockDim.x + threadIdx.x) >> 5;
    int lane = threadIdx.x & 31;
    if (warp >= GB * GN) return;
    const float* row = h + (size_t)warp * GC;
    float v0 = row[lane];
    float v1 = row[lane + 32];

    __nv_bfloat16 h0 = __float2bfloat16_rn(v0);
    __nv_bfloat16 h1 = __float2bfloat16_rn(v1);
    g_hh[warp * GC + lane]      = h0;
    g_hh[warp * GC + lane + 32] = h1;
    g_hl[warp * GC + lane]      = __float2bfloat16_rn(v0 - __bfloat162float(h0));
    g_hl[warp * GC + lane + 32] = __float2bfloat16_rn(v1 - __bfloat162float(h1));

    float p1 = v0 * a[lane]      + v1 * a[lane + 32];
    float p2 = v0 * a[GC + lane] + v1 * a[GC + lane + 32];
#pragma unroll
    for (int o = 16; o; o >>= 1) {
        p1 += __shfl_xor_sync(0xFFFFFFFFu, p1, o);
        p2 += __shfl_xor_sync(0xFFFFFFFFu, p2, o);
    }
    const float LOG2E = 1.4426950408889634f;
    if (lane == 0) {
        g_s1[warp] = p1 * LOG2E;
        g_s2[warp] = p2 * LOG2E;
    }
}

// ---------------------------------------------------------------- prefetch
static __device__ __forceinline__ void prefetch_tile(uint32_t bstg,
                                                     int b, int j0, int t) {
    const __nv_bfloat16* hh = g_hh + ((size_t)b * GN + j0) * GC;
    const __nv_bfloat16* hl = g_hl + ((size_t)b * GN + j0) * GC;
#pragma unroll
    for (int k = 0; k < 2; k++) {
        int q = t + 256 * k;
        int j = q >> 3, cc = q & 7;
        uint32_t off = sw128((uint32_t)(j * 128 + cc * 16));
        CP16(bstg + B_HI + off, hh + j * GC + cc * 8);
        CP16(bstg + B_LO + off, hl + j * GC + cc * 8);
    }
}

// phase-B chunk: one 4-element row-group, writes W stage, accumulates lsum.
#define PHASE_B_CHUNK(kidx, wdst, scale)                                      \
    {                                                                         \
        const int k = (kidx);                                                 \
        float e0 = s1r[k] + s2v.x; e0 = fmaxf(e0, ALPHA * e0);                \
        float e1 = s1r[k] + s2v.y; e1 = fmaxf(e1, ALPHA * e1);                \
        float e2 = s1r[k] + s2v.z; e2 = fmaxf(e2, ALPHA * e2);                \
        float e3 = s1r[k] + s2v.w; e3 = fmaxf(e3, ALPHA * e3);                \
        float w0 = (av[k].x > THRESH) ? fast_ex2(e0) : 0.0f;                  \
        float w1 = (av[k].y > THRESH) ? fast_ex2(e1) : 0.0f;                  \
        float w2 = (av[k].z > THRESH) ? fast_ex2(e2) : 0.0f;                  \
        float w3 = (av[k].w > THRESH) ? fast_ex2(e3) : 0.0f;                  \
        lsum[k] += (scale) * ((w0 + w1) + (w2 + w3));                         \
        uint32_t h01 = cvt_bf16x2(w0, w1);                                    \
        uint32_t h23 = cvt_bf16x2(w2, w3);                                    \
        float f0 = __uint_as_float(h01 << 16);                                \
        float f1 = __uint_as_float(h01 & 0xFFFF0000u);                        \
        float f2 = __uint_as_float(h23 << 16);                                \
        float f3 = __uint_as_float(h23 & 0xFFFF0000u);                        \
        uint32_t l01 = cvt_bf16x2(w0 - f0, w1 - f1);                          \
        uint32_t l23 = cvt_bf16x2(w2 - f2, w3 - f3);                          \
        asm volatile("st.shared.v2.b32 [%0], {%1,%2};"                        \
                     :: "r"((wdst) + W_HI + wbase + k * 2048),                \
                        "r"(h01), "r"(h23) : "memory");                       \
        asm volatile("st.shared.v2.b32 [%0], {%1,%2};"                        \
                     :: "r"((wdst) + W_LO + wbase + k * 2048),                \
                        "r"(l01), "r"(l23) : "memory");                       \
    }

// ---------------------------------------------------------------- kernel 2
__global__ __launch_bounds__(256, 2)
void gat_main_kernel(const float* __restrict__ adj,
                     float* __restrict__ out) {
    extern __shared__ char smem_raw[];
    __shared__ float sh_l[TI];

    const int t    = threadIdx.x;
    const int wid  = t >> 5;
    const int lane = t & 31;
    const int b    = blockIdx.y;
    const int i0   = blockIdx.x * TI;
    const int wm   = wid & 3;
    const int wn   = wid >> 2;

    uint32_t raw_u32 = smem_u32(smem_raw);
    uint32_t sbu = (raw_u32 + 1023u) & ~1023u;

    if (t < TI) sh_l[t] = 0.0f;

    const int r0  = t >> 4;
    const int jj0 = (t & 15) * 4;
    float s1r[4];
#pragma unroll
    for (int k = 0; k < 4; k++)
        s1r[k] = g_s1[b * GN + i0 + r0 + 16 * k];
    float lsum[4] = {0.f, 0.f, 0.f, 0.f};

    const float* ap0 = adj + (size_t)(i0 + r0)      * GN + jj0;
    const float* ap1 = ap0 + (size_t)16 * GN;
    const float* ap2 = ap0 + (size_t)32 * GN;
    const float* ap3 = ap0 + (size_t)48 * GN;
    const float* s2p = g_s2 + b * GN + jj0;

    const uint32_t xr     = (uint32_t)(lane & 7) << 4;
    const uint32_t a_base = (uint32_t)((wm * 16 + (lane & 15)) * 128 + (lane & 16));
    const uint32_t b_base = (uint32_t)((lane & 15) * 128 + (lane & 16) + wn * 64);
    const uint32_t wbase  = sw128((uint32_t)(r0 * 128 + jj0 * 2));

    float acc[4][4];
#pragma unroll
    for (int nn = 0; nn < 4; nn++)
#pragma unroll
        for (int q = 0; q < 4; q++) acc[nn][q] = 0.0f;

    // prologue: B(0), B(1) in flight; adj/s2(0); phaseB(0); adj/s2(1)
    prefetch_tile(sbu + 0 * BSTG_SZ, b, 0, t);
    CP_COMMIT();
    prefetch_tile(sbu + 1 * BSTG_SZ, b, TJ, t);
    CP_COMMIT();
    float4 av[4];
    float4 s2v;
    av[0] = __ldg((const float4*)ap0);
    av[1] = __ldg((const float4*)ap1);
    av[2] = __ldg((const float4*)ap2);
    av[3] = __ldg((const float4*)ap3);
    s2v   = __ldg((const float4*)s2p);
    {
        const uint32_t w0stg = sbu + W_BASE;   // stage 0
        PHASE_B_CHUNK(0, w0stg, 1.0f)
        PHASE_B_CHUNK(1, w0stg, 1.0f)
        PHASE_B_CHUNK(2, w0stg, 1.0f)
        PHASE_B_CHUNK(3, w0stg, 1.0f)
    }
    av[0] = __ldg((const float4*)(ap0 + TJ));
    av[1] = __ldg((const float4*)(ap1 + TJ));
    av[2] = __ldg((const float4*)(ap2 + TJ));
    av[3] = __ldg((const float4*)(ap3 + TJ));
    s2v   = __ldg((const float4*)(s2p + TJ));

    int bs = 0;
    for (int tile = 0; tile < NTILES; tile++) {
        const int s = tile & 1;
        const uint32_t wstg  = sbu + W_BASE + s * WSTG_SZ;        // MMA reads
        const uint32_t wstgW = sbu + W_BASE + (s ^ 1) * WSTG_SZ;  // phaseB(t+1)
        const uint32_t bstg  = sbu + bs * BSTG_SZ;

        CP_WAIT1();        // B(tile) complete
        __syncthreads();   // W(tile) visible; MMA(tile-1) done in all warps

        // prefetch B(tile+2) into stage freed by MMA(tile-1)
        {
            int bs2 = bs + 2; if (bs2 >= 3) bs2 -= 3;
            if (tile + 2 < NTILES)
                prefetch_tile(sbu + bs2 * BSTG_SZ, b, (tile + 2) * TJ, t);
            CP_COMMIT();
        }

        const float bmask = (tile + 1 < NTILES) ? 1.0f : 0.0f;
        const uint32_t whb = wstg + W_HI;
        const uint32_t wlb = wstg + W_LO;
        const uint32_t bhb = bstg + B_HI;
        const uint32_t blb = bstg + B_LO;

        // ---- merged block: MMA(tile) chunks interleaved with phaseB(tile+1) ----
#pragma unroll
        for (int kk = 0; kk < 4; kk++) {
            // MMA chunk kk
            uint32_t ahi[4], alo[4];
            uint32_t a_off = (a_base + kk * 32) ^ xr;
            ldmx4(ahi, whb + a_off);
            ldmx4(alo, wlb + a_off);
            uint32_t bh[8], bl[8];
#pragma unroll
            for (int np = 0; np < 2; np++) {
                uint32_t b_off = (b_base + kk * 2048 + np * 32) ^ xr;
                ldmx4t(&bh[np * 4], bhb + b_off);
                ldmx4t(&bl[np * 4], blb + b_off);
            }
#pragma unroll
            for (int nn = 0; nn < 4; nn++) {
                int base = (nn >> 1) * 4 + (nn & 1) * 2;
                mma_bf16(acc[nn], ahi, bh[base], bh[base + 1]);
                mma_bf16(acc[nn], ahi, bl[base], bl[base + 1]);
                mma_bf16(acc[nn], alo, bh[base], bh[base + 1]);
            }
            // phaseB chunk kk for tile+1 (independent of MMA chunk above)
            PHASE_B_CHUNK(kk, wstgW, bmask)
        }

        // issue adj + s2 loads for tile+2 (consumed next block's phaseB)
        {
            int jn = (tile + 2 < NTILES) ? (tile + 2) * TJ : 0;
            av[0] = __ldg((const float4*)(ap0 + jn));
            av[1] = __ldg((const float4*)(ap1 + jn));
            av[2] = __ldg((const float4*)(ap2 + jn));
            av[3] = __ldg((const float4*)(ap3 + jn));
            s2v   = __ldg((const float4*)(s2p + jn));
        }

        bs = (bs == 2) ? 0 : bs + 1;
    }

    // ---- row sums ----
#pragma unroll
    for (int k = 0; k < 4; k++)
        atomicAdd(&sh_l[r0 + 16 * k], lsum[k]);
    __syncthreads();

    // ---- epilogue: normalize + ELU + store ----
    {
        int g  = lane >> 2;
        int qc = (lane & 3) * 2;
        int ra = wm * 16 + g;
        int rb = ra + 8;
        float la = 1.0f / sh_l[ra];
        float lb = 1.0f / sh_l[rb];
        float* oa = out + ((size_t)b * GN + i0 + ra) * GC;
        float* ob = out + ((size_t)b * GN + i0 + rb) * GC;
#pragma unroll
        for (int nn = 0; nn < 4; nn++) {
            int c = wn * 32 + nn * 8 + qc;
            float v0 = acc[nn][0] * la, v1 = acc[nn][1] * la;
            float v2 = acc[nn][2] * lb, v3 = acc[nn][3] * lb;
            float2 pa, pb;
            pa.x = (v0 > 0.f) ? v0 : expm1f(v0);
            pa.y = (v1 > 0.f) ? v1 : expm1f(v1);
            pb.x = (v2 > 0.f) ? v2 : expm1f(v2);
            pb.y = (v3 > 0.f) ? v3 : expm1f(v3);
            *(float2*)(oa + c) = pa;
            *(float2*)(ob + c) = pb;
        }
    }
}

// ---------------------------------------------------------------- launch
extern "C" void kernel_launch(void* const* d_in, const int* in_sizes, int n_in,
                              void* d_out, int out_size) {
    const float* input = (const float*)d_in[0];   // (B, N, C)
    const float* adj   = (const float*)d_in[1];   // (N, N)
    const float* a     = (const float*)d_in[2];   // (2C, 1)
    float* out = (float*)d_out;                   // (B, N, C)

    gat_scores_kernel<<<(GB * GN) / 8, 256>>>(input, a);

    cudaFuncSetAttribute(gat_main_kernel,
                         cudaFuncAttributeMaxDynamicSharedMemorySize, DSMEM_BYTES);
    dim3 grid(GN / TI, GB);
    gat_main_kernel<<<grid, 256, DSMEM_BYTES>>>(adj, out);
}

// round 13
// speedup vs baseline: 1.0159x; 1.0159x over previous
#include <cuda_runtime.h>
#include <cuda_bf16.h>
#include <cstdint>

// GAT: B=4, N=4096, C=64
// out = elu( softmax_j( mask(adj>0.5, lrelu(s1+s2)) ) @ h )
// R12: R10 schedule + PRMT/LOP3 truncation hi-lo split + rolling pointers.

#define GB 4
#define GN 4096
#define GC 64
#define TI 64
#define TJ 64
#define NTILES (GN / TJ)
#define ALPHA 0.2f
#define THRESH 0.5f

#define BSTG_SZ 16384     // BH 8KB + BL 8KB
#define WSTG_SZ 16384     // WH 8KB + WL 8KB
#define B_HI    0
#define B_LO    8192
#define W_HI    0
#define W_LO    8192
#define W_BASE  (3 * BSTG_SZ)
#define DSMEM_BYTES (3 * BSTG_SZ + 2 * WSTG_SZ + 1024)

__device__ float g_s1[GB * GN];
__device__ float g_s2[GB * GN];
__device__ __nv_bfloat16 g_hh[GB * GN * GC];
__device__ __nv_bfloat16 g_hl[GB * GN * GC];

// ---------------------------------------------------------------- helpers
static __device__ __forceinline__ uint32_t smem_u32(const void* p) {
    uint32_t a;
    asm("{ .reg .u64 t; cvta.to.shared.u64 t, %1; cvt.u32.u64 %0, t; }"
        : "=r"(a) : "l"(p));
    return a;
}
static __device__ __forceinline__ float fast_ex2(float x) {
    float r; asm("ex2.approx.f32 %0, %1;" : "=f"(r) : "f"(x)); return r;
}
// packs {lo -> low16, hi -> high16} with round-to-nearest
static __device__ __forceinline__ uint32_t cvt_bf16x2(float lo, float hi) {
    uint32_t r;
    asm("cvt.rn.bf16x2.f32 %0, %1, %2;" : "=r"(r) : "f"(hi), "f"(lo));
    return r;
}
// packs the high 16 bits of a (-> low half) and b (-> high half): bf16 truncation
static __device__ __forceinline__ uint32_t prmt_hi16(uint32_t a, uint32_t b) {
    uint32_t r;
    asm("prmt.b32 %0, %1, %2, 0x7632;" : "=r"(r) : "r"(a), "r"(b));
    return r;
}
static __device__ __forceinline__ uint32_t sw128(uint32_t b) {
    return b ^ ((b >> 3) & 0x70);
}
#define CP16(dst, src) \
    asm volatile("cp.async.cg.shared.global [%0], [%1], 16;" \
                 :: "r"(dst), "l"(src) : "memory")
#define CP_COMMIT() asm volatile("cp.async.commit_group;" ::: "memory")
#define CP_WAIT1()  asm volatile("cp.async.wait_group 1;" ::: "memory")

static __device__ __forceinline__ void ldmx4(uint32_t* r, uint32_t addr) {
    asm volatile("ldmatrix.sync.aligned.m8n8.x4.shared.b16 {%0,%1,%2,%3}, [%4];"
        : "=r"(r[0]), "=r"(r[1]), "=r"(r[2]), "=r"(r[3]) : "r"(addr));
}
static __device__ __forceinline__ void ldmx4t(uint32_t* r, uint32_t addr) {
    asm volatile("ldmatrix.sync.aligned.m8n8.x4.trans.shared.b16 {%0,%1,%2,%3}, [%4];"
        : "=r"(r[0]), "=r"(r[1]), "=r"(r[2]), "=r"(r[3]) : "r"(addr));
}
static __device__ __forceinline__ void mma_bf16(float* d, const uint32_t* a,
                                                uint32_t b0, uint32_t b1) {
    asm volatile(
        "mma.sync.aligned.m16n8k16.row.col.f32.bf16.bf16.f32 "
        "{%0,%1,%2,%3}, {%4,%5,%6,%7}, {%8,%9}, {%0,%1,%2,%3};"
        : "+f"(d[0]), "+f"(d[1]), "+f"(d[2]), "+f"(d[3])
        : "r"(a[0]), "r"(a[1]), "r"(a[2]), "r"(a[3]), "r"(b0), "r"(b1));
}

// ---------------------------------------------------------------- kernel 1
__global__ void gat_scores_kernel(const float* __restrict__ h,
                                  const float* __restrict__ a) {
    int warp = (blockIdx.x * blockDim.x + threadIdx.x) >> 5;
    int lane = threadIdx.x & 31;
    if (warp >= GB * GN) return;
    const float* row = h + (size_t)warp * GC;
    float v0 = row[lane];
    float v1 = row[lane + 32];

    __nv_bfloat16 h0 = __float2bfloat16_rn(v0);
    __nv_bfloat16 h1 = __float2bfloat16_rn(v1);
    g_hh[warp * GC + lane]      = h0;
    g_hh[warp * GC + lane + 32] = h1;
    g_hl[warp * GC + lane]      = __float2bfloat16_rn(v0 - __bfloat162float(h0));
    g_hl[warp * GC + lane + 32] = __float2bfloat16_rn(v1 - __bfloat162float(h1));

    float p1 = v0 * a[lane]      + v1 * a[lane + 32];
    float p2 = v0 * a[GC + lane] + v1 * a[GC + lane + 32];
#pragma unroll
    for (int o = 16; o; o >>= 1) {
        p1 += __shfl_xor_sync(0xFFFFFFFFu, p1, o);
        p2 += __shfl_xor_sync(0xFFFFFFFFu, p2, o);
    }
    const float LOG2E = 1.4426950408889634f;
    if (lane == 0) {
        g_s1[warp] = p1 * LOG2E;
        g_s2[warp] = p2 * LOG2E;
    }
}

// ---------------------------------------------------------------- prefetch
// h hi/lo tiles (rolled pointers): 64 x 64 bf16 each, K-major SW128.
static __device__ __forceinline__ void prefetch_tile(uint32_t bstg,
                                                     const __nv_bfloat16* hh,
                                                     const __nv_bfloat16* hl,
                                                     int t) {
#pragma unroll
    for (int k = 0; k < 2; k++) {
        int q = t + 256 * k;
        int j = q >> 3, cc = q & 7;
        uint32_t off = sw128((uint32_t)(j * 128 + cc * 16));
        CP16(bstg + B_HI + off, hh + j * GC + cc * 8);
        CP16(bstg + B_LO + off, hl + j * GC + cc * 8);
    }
}

// ---------------------------------------------------------------- kernel 2
__global__ __launch_bounds__(256, 2)
void gat_main_kernel(const float* __restrict__ adj,
                     float* __restrict__ out) {
    extern __shared__ char smem_raw[];
    __shared__ float sh_l[TI];

    const int t    = threadIdx.x;
    const int wid  = t >> 5;
    const int lane = t & 31;
    const int b    = blockIdx.y;
    const int i0   = blockIdx.x * TI;
    const int wm   = wid & 3;
    const int wn   = wid >> 2;

    uint32_t raw_u32 = smem_u32(smem_raw);
    uint32_t sbu = (raw_u32 + 1023u) & ~1023u;

    if (t < TI) sh_l[t] = 0.0f;

    const int r0  = t >> 4;
    const int jj0 = (t & 15) * 4;
    float s1r[4];
#pragma unroll
    for (int k = 0; k < 4; k++)
        s1r[k] = g_s1[b * GN + i0 + r0 + 16 * k];
    float lsum[4] = {0.f, 0.f, 0.f, 0.f};

    // base + rolling pointers for adj / s2 (advance TJ floats per tile)
    const float* ab0 = adj + (size_t)(i0 + r0) * GN + jj0;
    const float* ab1 = ab0 + (size_t)16 * GN;
    const float* ab2 = ab0 + (size_t)32 * GN;
    const float* ab3 = ab0 + (size_t)48 * GN;
    const float* sb  = g_s2 + b * GN + jj0;

    // rolling h-tile prefetch pointers (advance TJ*GC per tile)
    const __nv_bfloat16* hhb = g_hh + (size_t)b * GN * GC;
    const __nv_bfloat16* hlb = g_hl + (size_t)b * GN * GC;

    const uint32_t xr     = (uint32_t)(lane & 7) << 4;
    const uint32_t a_base = (uint32_t)((wm * 16 + (lane & 15)) * 128 + (lane & 16));
    const uint32_t b_base = (uint32_t)((lane & 15) * 128 + (lane & 16) + wn * 64);
    const uint32_t wbase  = sw128((uint32_t)(r0 * 128 + jj0 * 2));

    float acc[4][4];
#pragma unroll
    for (int nn = 0; nn < 4; nn++)
#pragma unroll
        for (int q = 0; q < 4; q++) acc[nn][q] = 0.0f;

    // prologue: B(0), B(1) in flight; adj/s2(0) in regs
    prefetch_tile(sbu + 0 * BSTG_SZ, hhb, hlb, t);
    CP_COMMIT();
    prefetch_tile(sbu + 1 * BSTG_SZ, hhb + TJ * GC, hlb + TJ * GC, t);
    CP_COMMIT();
    float4 av[4];
    av[0] = __ldg((const float4*)ab0);
    av[1] = __ldg((const float4*)ab1);
    av[2] = __ldg((const float4*)ab2);
    av[3] = __ldg((const float4*)ab3);
    float4 s2v = __ldg((const float4*)sb);

    // rolling load pointers point at NEXT tile (tile 1)
    const float* p0 = ab0 + TJ;
    const float* p1 = ab1 + TJ;
    const float* p2 = ab2 + TJ;
    const float* p3 = ab3 + TJ;
    const float* ps = sb + TJ;
    // rolling prefetch pointers point at tile+2
    const __nv_bfloat16* phh = hhb + 2 * TJ * GC;
    const __nv_bfloat16* phl = hlb + 2 * TJ * GC;

    int bs = 0;    // B stage of current tile (tile % 3)
    for (int tile = 0; tile < NTILES; tile++) {
        const int s = tile & 1;
        const uint32_t wstg = sbu + W_BASE + s * WSTG_SZ;
        const uint32_t bstg = sbu + bs * BSTG_SZ;

        // ---- phase B: w tile (hi/lo bf16, K-major, SW128) from regs ----
#pragma unroll
        for (int k = 0; k < 4; k++) {
            float e0 = s1r[k] + s2v.x; e0 = fmaxf(e0, ALPHA * e0);
            float e1 = s1r[k] + s2v.y; e1 = fmaxf(e1, ALPHA * e1);
            float e2 = s1r[k] + s2v.z; e2 = fmaxf(e2, ALPHA * e2);
            float e3 = s1r[k] + s2v.w; e3 = fmaxf(e3, ALPHA * e3);
            float w0 = (av[k].x > THRESH) ? fast_ex2(e0) : 0.0f;
            float w1 = (av[k].y > THRESH) ? fast_ex2(e1) : 0.0f;
            float w2 = (av[k].z > THRESH) ? fast_ex2(e2) : 0.0f;
            float w3 = (av[k].w > THRESH) ? fast_ex2(e3) : 0.0f;
            lsum[k] += (w0 + w1) + (w2 + w3);
            uint32_t u0 = __float_as_uint(w0);
            uint32_t u1 = __float_as_uint(w1);
            uint32_t u2 = __float_as_uint(w2);
            uint32_t u3 = __float_as_uint(w3);
            // hi = truncate-to-bf16 (PRMT pack), lo = exact residue, rn pack
            uint32_t h01 = prmt_hi16(u0, u1);
            uint32_t h23 = prmt_hi16(u2, u3);
            float f0 = __uint_as_float(u0 & 0xFFFF0000u);
            float f1 = __uint_as_float(u1 & 0xFFFF0000u);
            float f2 = __uint_as_float(u2 & 0xFFFF0000u);
            float f3 = __uint_as_float(u3 & 0xFFFF0000u);
            uint32_t l01 = cvt_bf16x2(w0 - f0, w1 - f1);
            uint32_t l23 = cvt_bf16x2(w2 - f2, w3 - f3);
            asm volatile("st.shared.v2.b32 [%0], {%1,%2};"
                         :: "r"(wstg + W_HI + wbase + k * 2048),
                            "r"(h01), "r"(h23) : "memory");
            asm volatile("st.shared.v2.b32 [%0], {%1,%2};"
                         :: "r"(wstg + W_LO + wbase + k * 2048),
                            "r"(l01), "r"(l23) : "memory");
        }

        // ---- issue adj + s2 loads for NEXT tile (hidden under MMA) ----
        av[0] = __ldg((const float4*)p0);
        av[1] = __ldg((const float4*)p1);
        av[2] = __ldg((const float4*)p2);
        av[3] = __ldg((const float4*)p3);
        s2v   = __ldg((const float4*)ps);
        if (tile + 2 >= NTILES) {          // wrap: next loads (unused) -> tile 0
            p0 = ab0; p1 = ab1; p2 = ab2; p3 = ab3; ps = sb;
        } else {
            p0 += TJ; p1 += TJ; p2 += TJ; p3 += TJ; ps += TJ;
        }

        CP_WAIT1();        // B(tile) done (B(tile+1) may remain in flight)
        __syncthreads();   // W + B visible; all warps past mma(tile-1)

        // ---- prefetch B(tile+2) into the stage freed by mma(tile-1) ----
        if (tile + 2 < NTILES) {
            int bs2 = bs + 2; if (bs2 >= 3) bs2 -= 3;
            prefetch_tile(sbu + bs2 * BSTG_SZ, phh, phl, t);
            phh += TJ * GC; phl += TJ * GC;
        }
        CP_COMMIT();

        // ---- MMA phase: 3-term bf16, warp tile 16x32 ----
        {
            const uint32_t whb = wstg + W_HI;
            const uint32_t wlb = wstg + W_LO;
            const uint32_t bhb = bstg + B_HI;
            const uint32_t blb = bstg + B_LO;
#pragma unroll
            for (int kk = 0; kk < 4; kk++) {
                uint32_t ahi[4], alo[4];
                uint32_t a_off = (a_base + kk * 32) ^ xr;
                ldmx4(ahi, whb + a_off);
                ldmx4(alo, wlb + a_off);
                uint32_t bh[8], bl[8];
#pragma unroll
                for (int np = 0; np < 2; np++) {
                    uint32_t b_off = (b_base + kk * 2048 + np * 32) ^ xr;
                    ldmx4t(&bh[np * 4], bhb + b_off);
                    ldmx4t(&bl[np * 4], blb + b_off);
                }
#pragma unroll
                for (int nn = 0; nn < 4; nn++) {
                    int base = (nn >> 1) * 4 + (nn & 1) * 2;
                    mma_bf16(acc[nn], ahi, bh[base], bh[base + 1]);
                    mma_bf16(acc[nn], ahi, bl[base], bl[base + 1]);
                    mma_bf16(acc[nn], alo, bh[base], bh[base + 1]);
                }
            }
        }

        bs = (bs == 2) ? 0 : bs + 1;
    }

    // ---- row sums ----
#pragma unroll
    for (int k = 0; k < 4; k++)
        atomicAdd(&sh_l[r0 + 16 * k], lsum[k]);
    __syncthreads();

    // ---- epilogue: normalize + ELU + store ----
    {
        int g  = lane >> 2;
        int qc = (lane & 3) * 2;
        int ra = wm * 16 + g;
        int rb = ra + 8;
        float la = 1.0f / sh_l[ra];
        float lb = 1.0f / sh_l[rb];
        float* oa = out + ((size_t)b * GN + i0 + ra) * GC;
        float* ob = out + ((size_t)b * GN + i0 + rb) * GC;
#pragma unroll
        for (int nn = 0; nn < 4; nn++) {
            int c = wn * 32 + nn * 8 + qc;
            float v0 = acc[nn][0] * la, v1 = acc[nn][1] * la;
            float v2 = acc[nn][2] * lb, v3 = acc[nn][3] * lb;
            float2 pa, pb;
            pa.x = (v0 > 0.f) ? v0 : expm1f(v0);
            pa.y = (v1 > 0.f) ? v1 : expm1f(v1);
            pb.x = (v2 > 0.f) ? v2 : expm1f(v2);
            pb.y = (v3 > 0.f) ? v3 : expm1f(v3);
            *(float2*)(oa + c) = pa;
            *(float2*)(ob + c) = pb;
        }
    }
}

// ---------------------------------------------------------------- launch
extern "C" void kernel_launch(void* const* d_in, const int* in_sizes, int n_in,
                              void* d_out, int out_size) {
    const float* input = (const float*)d_in[0];   // (B, N, C)
    const float* adj   = (const float*)d_in[1];   // (N, N)
    const float* a     = (const float*)d_in[2];   // (2C, 1)
    float* out = (float*)d_out;                   // (B, N, C)

    gat_scores_kernel<<<(GB * GN) / 8, 256>>>(input, a);

    cudaFuncSetAttribute(gat_main_kernel,
                         cudaFuncAttributeMaxDynamicSharedMemorySize, DSMEM_BYTES);
    dim3 grid(GN / TI, GB);
    gat_main_kernel<<<grid, 256, DSMEM_BYTES>>>(adj, out);
}